// round 1
// baseline (speedup 1.0000x reference)
#include <cuda_runtime.h>
#include <cuda_bf16.h>
#include <cstdint>
#include <math.h>

// Problem constants
#define LL 128
#define BB 512
#define DD 512
#define SS 128
#define LB (LL * BB)   // 65536

// -------- device scratch (static allocations are allowed) --------
__device__ __align__(16) float          g_A[SS * SS];        // exp(log-normalized tparams), [i][j]
__device__ __align__(16) float          g_colbias[SS];       // c - 0.5 * sum_d mu^2/var
__device__ __align__(16) float          g_rvar[DD];          // 1/var
__device__ __align__(16) float          g_xq[LB];            // -0.5 * sum_d x^2/var
__device__ __align__(16) __nv_bfloat16  g_Xs[(size_t)LB * DD];   // x cast to bf16 (64 MB)
__device__ __align__(16) __nv_bfloat16  g_Mv[SS * DD];       // mu/var in bf16, [s][d]
__device__ __align__(16) float          g_density[(size_t)LB * SS]; // 32 MB
__device__ __align__(16) float          g_perb[BB];          // per-batch logsumexp

// log(2*pi)
#define LOG2PI 1.8378770664093453f
// -log(128)
#define LOGPI_INIT (-4.852030263919617f)

// =====================================================================
// Kernel 1: preprocessing (1 block, 512 threads)
// =====================================================================
__global__ void prep_kernel(const float* __restrict__ tparams,
                            const float* __restrict__ means,
                            const float* __restrict__ var) {
    __shared__ float sred[512];
    int t = threadIdx.x;

    float v = var[t];
    g_rvar[t] = 1.0f / v;
    sred[t] = logf(v);
    __syncthreads();
    for (int off = 256; off > 0; off >>= 1) {
        if (t < off) sred[t] += sred[t + off];
        __syncthreads();
    }
    float slv = sred[0];
    float c = -256.0f * LOG2PI - 0.5f * slv;   // D/2 = 256

    int q   = t & 3;      // 0..3
    int grp = t >> 2;     // 0..127

    // col bias: c - 0.5 * sum_d mu[s,d]^2 / var[d]
    {
        float mq = 0.f;
        for (int d = q; d < DD; d += 4) {
            float m = means[grp * DD + d];
            mq += m * m * g_rvar[d];
        }
        mq += __shfl_xor_sync(0xffffffffu, mq, 1);
        mq += __shfl_xor_sync(0xffffffffu, mq, 2);
        if (q == 0) g_colbias[grp] = c - 0.5f * mq;
    }

    // A = exp(tparams - logsumexp(tparams, axis=1))
    {
        float mx = -1e30f;
        for (int jj = q; jj < SS; jj += 4) mx = fmaxf(mx, tparams[grp * SS + jj]);
        mx = fmaxf(mx, __shfl_xor_sync(0xffffffffu, mx, 1));
        mx = fmaxf(mx, __shfl_xor_sync(0xffffffffu, mx, 2));
        float se = 0.f;
        for (int jj = q; jj < SS; jj += 4) se += __expf(tparams[grp * SS + jj] - mx);
        se += __shfl_xor_sync(0xffffffffu, se, 1);
        se += __shfl_xor_sync(0xffffffffu, se, 2);
        float lse = mx + __logf(se);
        for (int jj = q; jj < SS; jj += 4)
            g_A[grp * SS + jj] = __expf(tparams[grp * SS + jj] - lse);
    }

    // Mv = mu / var in bf16
    for (int idx = t; idx < SS * DD; idx += 512) {
        int d = idx & (DD - 1);
        g_Mv[idx] = __float2bfloat16(means[idx] * g_rvar[d]);
    }
}

// =====================================================================
// Kernel 2: per-row -0.5*sum(x^2/var) + bf16 cast of X
// grid = LB/8 blocks, 256 threads (8 warps, 1 row per warp)
// =====================================================================
__global__ __launch_bounds__(256) void xqcast_kernel(const float* __restrict__ sents) {
    __shared__ __align__(16) float srv[DD];
    int tid = threadIdx.x;
    for (int i = tid; i < DD; i += 256) srv[i] = g_rvar[i];
    __syncthreads();

    int warp = tid >> 5, lane = tid & 31;
    int row = blockIdx.x * 8 + warp;

    const float4* src = reinterpret_cast<const float4*>(sents + (size_t)row * DD);
    float sum = 0.f;
#pragma unroll
    for (int c = 0; c < 4; ++c) {
        int idx4 = c * 32 + lane;   // float4 index in row (128 per row)
        float4 x  = src[idx4];
        float4 rv = *reinterpret_cast<const float4*>(&srv[idx4 * 4]);
        sum += x.x * x.x * rv.x + x.y * x.y * rv.y + x.z * x.z * rv.z + x.w * x.w * rv.w;
        __nv_bfloat162 p0 = __float22bfloat162_rn(make_float2(x.x, x.y));
        __nv_bfloat162 p1 = __float22bfloat162_rn(make_float2(x.z, x.w));
        __nv_bfloat162* dst = reinterpret_cast<__nv_bfloat162*>(&g_Xs[(size_t)row * DD + idx4 * 4]);
        dst[0] = p0;
        dst[1] = p1;
    }
#pragma unroll
    for (int off = 16; off > 0; off >>= 1)
        sum += __shfl_xor_sync(0xffffffffu, sum, off);
    if (lane == 0) g_xq[row] = -0.5f * sum;
}

// =====================================================================
// Kernel 3: density GEMM: density[lb][s] = Xs[lb][:] . Mv[s][:] + xq[lb] + colbias[s]
// bf16 mma.sync m16n8k16. Block tile 128x128, K chunks of 64. 256 threads / 8 warps.
// =====================================================================
__device__ __forceinline__ void mma_bf16(float& c0, float& c1, float& c2, float& c3,
                                         uint32_t a0, uint32_t a1, uint32_t a2, uint32_t a3,
                                         uint32_t b0, uint32_t b1) {
    asm volatile(
        "mma.sync.aligned.m16n8k16.row.col.f32.bf16.bf16.f32 "
        "{%0,%1,%2,%3}, {%4,%5,%6,%7}, {%8,%9}, {%0,%1,%2,%3};\n"
        : "+f"(c0), "+f"(c1), "+f"(c2), "+f"(c3)
        : "r"(a0), "r"(a1), "r"(a2), "r"(a3), "r"(b0), "r"(b1));
}

#define SMSTRIDE 72  // padded row stride in bf16 elems (144 B -> conflict-free frags)

__global__ __launch_bounds__(256) void density_kernel() {
    __shared__ __align__(16) __nv_bfloat16 sA[128 * SMSTRIDE];
    __shared__ __align__(16) __nv_bfloat16 sB[128 * SMSTRIDE];
    int tid  = threadIdx.x;
    int warp = tid >> 5, lane = tid & 31;
    int g = lane >> 2, tg = lane & 3;
    int mbase = blockIdx.x * 128;

    float acc[16][4];
#pragma unroll
    for (int n = 0; n < 16; ++n)
#pragma unroll
        for (int k = 0; k < 4; ++k) acc[n][k] = 0.f;

    for (int ko = 0; ko < 8; ++ko) {
        // stage 128x64 tiles of Xs and Mv
        for (int i = tid; i < 1024; i += 256) {
            int r = i >> 3, c8 = i & 7;
            uint4 va = *reinterpret_cast<const uint4*>(&g_Xs[(size_t)(mbase + r) * DD + ko * 64 + c8 * 8]);
            *reinterpret_cast<uint4*>(&sA[r * SMSTRIDE + c8 * 8]) = va;
            uint4 vb = *reinterpret_cast<const uint4*>(&g_Mv[(size_t)r * DD + ko * 64 + c8 * 8]);
            *reinterpret_cast<uint4*>(&sB[r * SMSTRIDE + c8 * 8]) = vb;
        }
        __syncthreads();
#pragma unroll
        for (int ks = 0; ks < 4; ++ks) {
            int k0 = ks * 16 + tg * 2;
            uint32_t a0 = *reinterpret_cast<const uint32_t*>(&sA[(warp * 16 + g)     * SMSTRIDE + k0]);
            uint32_t a1 = *reinterpret_cast<const uint32_t*>(&sA[(warp * 16 + g + 8) * SMSTRIDE + k0]);
            uint32_t a2 = *reinterpret_cast<const uint32_t*>(&sA[(warp * 16 + g)     * SMSTRIDE + k0 + 8]);
            uint32_t a3 = *reinterpret_cast<const uint32_t*>(&sA[(warp * 16 + g + 8) * SMSTRIDE + k0 + 8]);
#pragma unroll
            for (int n = 0; n < 16; ++n) {
                uint32_t b0 = *reinterpret_cast<const uint32_t*>(&sB[(n * 8 + g) * SMSTRIDE + k0]);
                uint32_t b1 = *reinterpret_cast<const uint32_t*>(&sB[(n * 8 + g) * SMSTRIDE + k0 + 8]);
                mma_bf16(acc[n][0], acc[n][1], acc[n][2], acc[n][3], a0, a1, a2, a3, b0, b1);
            }
        }
        __syncthreads();
    }

    int r0 = mbase + warp * 16 + g;
    int r1 = r0 + 8;
    float xq0 = g_xq[r0], xq1 = g_xq[r1];
#pragma unroll
    for (int n = 0; n < 16; ++n) {
        int col = n * 8 + tg * 2;
        float cb0 = g_colbias[col], cb1 = g_colbias[col + 1];
        g_density[(size_t)r0 * SS + col]     = acc[n][0] + xq0 + cb0;
        g_density[(size_t)r0 * SS + col + 1] = acc[n][1] + xq0 + cb1;
        g_density[(size_t)r1 * SS + col]     = acc[n][2] + xq1 + cb0;
        g_density[(size_t)r1 * SS + col + 1] = acc[n][3] + xq1 + cb1;
    }
}

// =====================================================================
// Kernel 4: forward recurrence. 256 blocks, 2 batch rows each, 128 threads.
// Dynamic smem: A fp32 (64 KB) + p (128 float2) + 16-float reduce scratch.
// =====================================================================
#define RECUR_SMEM (16384 * 4 + 256 * 4 + 16 * 4)

__global__ __launch_bounds__(128) void recur_kernel(const float* __restrict__ masks) {
    extern __shared__ float sh[];
    float*  shA  = sh;                       // 16384 floats
    float2* sp   = reinterpret_cast<float2*>(sh + 16384); // 128 float2
    float*  sred = sh + 16384 + 256;         // 16 floats

    int j = threadIdx.x;
    int warp = j >> 5, lane = j & 31;
    int b0g = blockIdx.x * 2;
    int b1g = b0g + 1;

    for (int i = j; i < SS * SS; i += 128) shA[i] = g_A[i];

    float al0 = LOGPI_INIT + g_density[(size_t)b0g * SS + j];
    float al1 = LOGPI_INIT + g_density[(size_t)b1g * SS + j];
    __syncthreads();

    for (int l = 1; l < LL; ++l) {
        // block-wide max per batch row
        float m0 = al0, m1 = al1;
#pragma unroll
        for (int off = 16; off > 0; off >>= 1) {
            m0 = fmaxf(m0, __shfl_xor_sync(0xffffffffu, m0, off));
            m1 = fmaxf(m1, __shfl_xor_sync(0xffffffffu, m1, off));
        }
        if (lane == 0) { sred[warp] = m0; sred[4 + warp] = m1; }
        __syncthreads();
        m0 = fmaxf(fmaxf(sred[0], sred[1]), fmaxf(sred[2], sred[3]));
        m1 = fmaxf(fmaxf(sred[4], sred[5]), fmaxf(sred[6], sred[7]));

        sp[j] = make_float2(__expf(al0 - m0), __expf(al1 - m1));
        __syncthreads();

        float acc0 = 0.f, acc1 = 0.f;
#pragma unroll 8
        for (int i = 0; i < SS; ++i) {
            float  av = shA[i * SS + j];
            float2 pv = sp[i];
            acc0 = fmaf(pv.x, av, acc0);
            acc1 = fmaf(pv.y, av, acc1);
        }

        size_t base = (size_t)l * BB * SS;
        float d0 = g_density[base + (size_t)b0g * SS + j];
        float d1 = g_density[base + (size_t)b1g * SS + j];
        float mk0 = masks[l * BB + b0g];
        float mk1 = masks[l * BB + b1g];
        float na0 = d0 + m0 + __logf(acc0);
        float na1 = d1 + m1 + __logf(acc1);
        al0 = mk0 * na0 + (1.f - mk0) * al0;
        al1 = mk1 * na1 + (1.f - mk1) * al1;
    }

    // final per-batch logsumexp over states
    float m0 = al0, m1 = al1;
#pragma unroll
    for (int off = 16; off > 0; off >>= 1) {
        m0 = fmaxf(m0, __shfl_xor_sync(0xffffffffu, m0, off));
        m1 = fmaxf(m1, __shfl_xor_sync(0xffffffffu, m1, off));
    }
    if (lane == 0) { sred[warp] = m0; sred[4 + warp] = m1; }
    __syncthreads();
    m0 = fmaxf(fmaxf(sred[0], sred[1]), fmaxf(sred[2], sred[3]));
    m1 = fmaxf(fmaxf(sred[4], sred[5]), fmaxf(sred[6], sred[7]));
    float e0 = __expf(al0 - m0), e1 = __expf(al1 - m1);
#pragma unroll
    for (int off = 16; off > 0; off >>= 1) {
        e0 += __shfl_xor_sync(0xffffffffu, e0, off);
        e1 += __shfl_xor_sync(0xffffffffu, e1, off);
    }
    __syncthreads();
    if (lane == 0) { sred[8 + warp] = e0; sred[12 + warp] = e1; }
    __syncthreads();
    if (j == 0) {
        float s0 = sred[8] + sred[9] + sred[10] + sred[11];
        float s1 = sred[12] + sred[13] + sred[14] + sred[15];
        g_perb[b0g] = m0 + __logf(s0);
        g_perb[b1g] = m1 + __logf(s1);
    }
}

// =====================================================================
// Kernel 5: deterministic final reduction over 512 batch rows
// =====================================================================
__global__ void finalize_kernel(float* __restrict__ out, int out_size) {
    __shared__ float s[256];
    int t = threadIdx.x;
    s[t] = g_perb[t] + g_perb[t + 256];
    __syncthreads();
    for (int off = 128; off > 0; off >>= 1) {
        if (t < off) s[t] += s[t + off];
        __syncthreads();
    }
    for (int i = t; i < out_size; i += 256)
        if (i != 0) out[i] = 0.f;   // jacobian_loss = 0
    if (t == 0) out[0] = s[0];
}

// =====================================================================
extern "C" void kernel_launch(void* const* d_in, const int* in_sizes, int n_in,
                              void* d_out, int out_size) {
    const float* sents   = (const float*)d_in[0];
    const float* masks   = (const float*)d_in[1];
    const float* tparams = (const float*)d_in[2];
    const float* means   = (const float*)d_in[3];
    const float* var     = (const float*)d_in[4];
    float* out = (float*)d_out;

    cudaFuncSetAttribute(recur_kernel, cudaFuncAttributeMaxDynamicSharedMemorySize, RECUR_SMEM);

    prep_kernel<<<1, 512>>>(tparams, means, var);
    xqcast_kernel<<<LB / 8, 256>>>(sents);
    density_kernel<<<LB / 128, 256>>>();
    recur_kernel<<<BB / 2, 128, RECUR_SMEM>>>(masks);
    finalize_kernel<<<1, 256>>>(out, out_size);
}